// round 13
// baseline (speedup 1.0000x reference)
#include <cuda_runtime.h>
#include <cstdint>

#define NB     8
#define NVOX   65536
#define GRIDSZ 64
#define G3     (GRIDSZ*GRIDSZ*GRIDSZ)
#define BNTOT  (NB*NVOX)
#define C      16
#define EPSF   1e-3f
#define TILE   1024
#define NTILES (BNTOT/TILE)          // 512
#define NBKT   (NTILES*27)           // 13824
#define STSTR  20                    // staging row stride (floats)

// ---------------- static scratch (no allocation) ----------------
__device__ int   g_idx_map[NB*G3];                 // 8.4 MB
__device__ int   g_pairs[(size_t)NBKT*TILE];       // 56.6 MB: (local<<16)|in_row per (tile,o)
__device__ int   g_cnt[NBKT];
__device__ int   g_nbmask[BNTOT];                  // 2 MB: 27-bit active-neighbor mask
__device__ float g_t0[(size_t)BNTOT*C];            // 33.5 MB pre-BN layer-0
__device__ float g_t1[(size_t)BNTOT*C];            // 33.5 MB pre-BN layer-1
__device__ float g_stats[2*C];                     // [sum16, sumsq16] (zeroed by finalize)
__device__ float g_affine[2*C];                    // [A16, B16]

// ---------------- f32x2 helpers ----------------
__device__ __forceinline__ unsigned long long fma2(unsigned long long a,
                                                   unsigned long long b,
                                                   unsigned long long c) {
    unsigned long long d;
    asm("fma.rn.f32x2 %0, %1, %2, %3;" : "=l"(d) : "l"(a), "l"(b), "l"(c));
    return d;
}
__device__ __forceinline__ unsigned long long bcast2(float x) {
    unsigned long long d; unsigned r = __float_as_uint(x);
    asm("mov.b64 %0, {%1, %2};" : "=l"(d) : "r"(r), "r"(r));
    return d;
}

// ---------------- phase 0: hash map ----------------
__global__ void k_init_map() {
    int i = blockIdx.x * blockDim.x + threadIdx.x;
    reinterpret_cast<int4*>(g_idx_map)[i] = make_int4(-1, -1, -1, -1);
}

__global__ void k_scatter(const int* __restrict__ xyz, const int* __restrict__ nv) {
    int bn = blockIdx.x * blockDim.x + threadIdx.x;
    int b = bn >> 16, n = bn & 0xFFFF;
    if (n < nv[b]) {
        const int* c = xyz + (size_t)bn * 3;
        g_idx_map[b * G3 + c[0] * (GRIDSZ*GRIDSZ) + c[1] * GRIDSZ + c[2]] = n;
    }
}

// ---------------- phase 1: per-(tile,o) rulebook + neighbor mask ----------------
__global__ __launch_bounds__(1024)
void k_build(const int* __restrict__ xyz, const int* __restrict__ nv) {
    __shared__ int s_cnt[27];
    int tid = threadIdx.x;
    if (tid < 27) s_cnt[tid] = 0;
    __syncthreads();

    int bn = blockIdx.x * TILE + tid;
    int b  = bn >> 16, n = bn & 0xFFFF;
    bool valid = n < nv[b];
    int x = 0, y = 0, z = 0, base = b * G3;
    if (valid) {
        const int* c = xyz + (size_t)bn * 3;
        x = c[0]; y = c[1]; z = c[2];
    }
    int tilebase = blockIdx.x * 27;
    int lane = tid & 31;
    int mask = 0;

    #pragma unroll
    for (int o = 0; o < 27; ++o) {
        int dx = o / 9 - 1, dy = (o / 3) % 3 - 1, dz = o % 3 - 1;
        int idx = -1;
        if (valid) {
            int nx = x + dx, ny = y + dy, nz = z + dz;
            if (((unsigned)nx < GRIDSZ) & ((unsigned)ny < GRIDSZ) & ((unsigned)nz < GRIDSZ))
                idx = g_idx_map[base + nx * (GRIDSZ*GRIDSZ) + ny * GRIDSZ + nz];
        }
        unsigned m = __ballot_sync(0xFFFFFFFFu, idx >= 0);
        if (m) {
            int leader = __ffs(m) - 1;
            int basepos = 0;
            if (lane == leader) basepos = atomicAdd(&s_cnt[o], __popc(m));
            basepos = __shfl_sync(0xFFFFFFFFu, basepos, leader);
            if (idx >= 0) {
                int nbefore = __popc(m & ((1u << lane) - 1u));
                g_pairs[((size_t)(tilebase + o) << 10) + basepos + nbefore] = (tid << 16) | idx;
                mask |= 1 << o;
            }
        }
    }
    g_nbmask[bn] = mask;
    __syncthreads();
    if (tid < 27) g_cnt[tilebase + tid] = s_cnt[tid];
}

// ---------------- conv (half of output channels per block) ----------------
// smem floats: acc TILE*8 | w 27*128 | stage 8*32*STSTR | nw 32 | aff 32
#define SM_FLOATS (TILE*8 + 27*128 + 8*32*STSTR + 32 + 32)
#define SM_BYTES  (SM_FLOATS * 4)

template<bool AFF>
__global__ __launch_bounds__(256, 3)
void k_conv(const float* __restrict__ feats, const float* __restrict__ w,
            const float* __restrict__ nw, const float* __restrict__ affine,
            float* __restrict__ tout) {
    extern __shared__ float sm[];
    float* s_acc   = sm;                      // TILE*8: row r, chunk c at r*8+((c^(r&1))<<2)
    float* s_w     = sm + TILE*8;             // 27 x 16ci x 8co (this half)
    float* s_stage = s_w + 27*128;            // 8 warps x 32 rows x STSTR
    float* s_nw    = s_stage + 8*32*STSTR;
    float* s_aff   = s_nw + 32;

    int tid  = threadIdx.x;
    int tile = blockIdx.x >> 1;
    int half = blockIdx.x & 1;

    for (int i = tid; i < 27*128; i += 256) {
        int o = i >> 7, r = i & 127, ci = r >> 3, j = r & 7;
        s_w[i] = w[o * 256 + ci * 16 + half * 8 + j];
    }
    if (tid < 27) s_nw[tid] = nw[tid];
    if (AFF && tid < 32) s_aff[tid] = affine[tid];
    for (int i = tid; i < TILE*8; i += 256) s_acc[i] = 0.0f;
    __syncthreads();

    int b = tile >> 6;                        // 64 tiles per batch
    const float* fb = feats + (size_t)b * NVOX * C;

    int wi = tid >> 5, lane = tid & 31;
    float* stW = s_stage + wi * (32 * STSTR);
    int qsub = lane & 3;
    int rsub = lane >> 2;

    for (int o = 0; o < 27; ++o) {
        int bkt = tile * 27 + o;
        int cnt = g_cnt[bkt];
        const int* pl = g_pairs + ((size_t)bkt << 10);
        const ulonglong2* wbase = reinterpret_cast<const ulonglong2*>(s_w + o * 128);

        int base = wi * 32;
        if (base < cnt) {
            int pc = (base + lane < cnt) ? pl[base + lane] : 0;
            float4 V[4];
            #pragma unroll
            for (int k = 0; k < 4; ++k) {
                int rk = __shfl_sync(0xFFFFFFFFu, pc, rsub + 8*k) & 0xFFFF;
                V[k] = __ldg(reinterpret_cast<const float4*>(fb + (size_t)rk * C) + qsub);
            }
            while (base < cnt) {
                __syncwarp();
                #pragma unroll
                for (int k = 0; k < 4; ++k)
                    *reinterpret_cast<float4*>(stW + (rsub + 8*k) * STSTR + qsub * 4) = V[k];
                __syncwarp();

                int nbase = base + 256;
                int pn = (nbase + lane < cnt) ? pl[nbase + lane] : 0;
                #pragma unroll
                for (int k = 0; k < 4; ++k) {
                    int rk = __shfl_sync(0xFFFFFFFFu, pn, rsub + 8*k) & 0xFFFF;
                    V[k] = __ldg(reinterpret_cast<const float4*>(fb + (size_t)rk * C) + qsub);
                }

                if (base + lane < cnt) {
                    float fv[16];
                    #pragma unroll
                    for (int q = 0; q < 4; ++q)
                        *reinterpret_cast<float4*>(fv + 4*q) =
                            *reinterpret_cast<const float4*>(stW + lane * STSTR + q * 4);
                    if (AFF) {
                        #pragma unroll
                        for (int ci = 0; ci < 16; ++ci)
                            fv[ci] = fmaxf(0.0f, fv[ci] * s_aff[ci] + s_aff[16 + ci]);
                    }
                    int local = pc >> 16;
                    int s = local & 1;
                    float* arow = s_acc + local * 8;
                    ulonglong2 a0 = *reinterpret_cast<ulonglong2*>(arow + ((0^s) << 2));
                    ulonglong2 a1 = *reinterpret_cast<ulonglong2*>(arow + ((1^s) << 2));
                    unsigned long long c0=a0.x, c1=a0.y, c2=a1.x, c3=a1.y;
                    #pragma unroll
                    for (int ci = 0; ci < 16; ++ci) {
                        unsigned long long am = bcast2(fv[ci]);
                        ulonglong2 w01 = wbase[ci*2+0], w23 = wbase[ci*2+1];
                        c0 = fma2(am, w01.x, c0);  c1 = fma2(am, w01.y, c1);
                        c2 = fma2(am, w23.x, c2);  c3 = fma2(am, w23.y, c3);
                    }
                    *reinterpret_cast<ulonglong2*>(arow + ((0^s) << 2)) = make_ulonglong2(c0, c1);
                    *reinterpret_cast<ulonglong2*>(arow + ((1^s) << 2)) = make_ulonglong2(c2, c3);
                }
                base = nbase; pc = pn;
            }
        }
        __syncthreads();
    }

    // epilogue: norm-div, write this half's 8 channels, BN partials (8 ch)
    float ps[8], pq[8];
    #pragma unroll
    for (int c2 = 0; c2 < 8; ++c2) { ps[c2] = 0.0f; pq[c2] = 0.0f; }

    #pragma unroll
    for (int k = 0; k < 4; ++k) {
        int i = tid + k * 256;
        int m = g_nbmask[tile * TILE + i];
        float nsum = 0.0f;
        #pragma unroll
        for (int o = 0; o < 27; ++o)
            nsum += ((m >> o) & 1) ? s_nw[o] : 0.0f;
        float inv = 1.0f / (1.0f + fabsf(nsum));
        int s = i & 1;
        const float* ar = s_acc + i * 8;
        float4* to = reinterpret_cast<float4*>(tout + (size_t)(tile * TILE + i) * C) + half * 2;
        #pragma unroll
        for (int q = 0; q < 2; ++q) {
            float4 v = *reinterpret_cast<const float4*>(ar + ((q^s) << 2));
            float x0 = v.x*inv, x1 = v.y*inv, x2 = v.z*inv, x3 = v.w*inv;
            to[q] = make_float4(x0, x1, x2, x3);
            ps[4*q+0] += x0; pq[4*q+0] += x0*x0;
            ps[4*q+1] += x1; pq[4*q+1] += x1*x1;
            ps[4*q+2] += x2; pq[4*q+2] += x2*x2;
            ps[4*q+3] += x3; pq[4*q+3] += x3*x3;
        }
    }
    #pragma unroll
    for (int off = 16; off; off >>= 1) {
        #pragma unroll
        for (int c2 = 0; c2 < 8; ++c2) {
            ps[c2] += __shfl_xor_sync(0xFFFFFFFFu, ps[c2], off);
            pq[c2] += __shfl_xor_sync(0xFFFFFFFFu, pq[c2], off);
        }
    }
    __syncthreads();
    float* s_red = s_stage;            // reuse: 8 warps x 16 floats
    if ((tid & 31) == 0) {
        #pragma unroll
        for (int c2 = 0; c2 < 8; ++c2) {
            s_red[wi*16 + c2]     = ps[c2];
            s_red[wi*16 + 8 + c2] = pq[c2];
        }
    }
    __syncthreads();
    if (tid < 16) {
        float a = 0.0f;
        #pragma unroll
        for (int w8 = 0; w8 < 8; ++w8) a += s_red[w8*16 + tid];
        int ch = (tid & 7) + half * 8;
        atomicAdd(&g_stats[(tid < 8) ? ch : 16 + ch], a);
    }
}

// ---------------- BN finalize (reads stats, writes affine, re-zeroes stats) ----------------
__global__ void k_finalize(const float* __restrict__ gamma,
                           const float* __restrict__ beta,
                           const int* __restrict__ nv) {
    int i = threadIdx.x;   // 32 threads
    float A = 0.0f, Bv = 0.0f;
    if (i < C) {
        float cnt = 0.0f;
        #pragma unroll
        for (int b = 0; b < NB; ++b) cnt += (float)nv[b];
        float mean = g_stats[i] / cnt;
        float var  = g_stats[C + i] / cnt - mean * mean;
        A  = rsqrtf(var + EPSF) * gamma[i];
        Bv = beta[i] - mean * A;
    }
    __syncwarp();
    if (i < C) { g_affine[i] = A; g_affine[C + i] = Bv; }
    g_stats[i] = 0.0f;     // replay-safe
}

// ---------------- final affine+relu+mask ----------------
__global__ __launch_bounds__(256)
void k_apply(const float* __restrict__ t, const int* __restrict__ nv,
             float* __restrict__ out) {
    __shared__ float sA[32];
    if (threadIdx.x < 32) sA[threadIdx.x] = g_affine[threadIdx.x];
    __syncthreads();
    int bn = blockIdx.x * 256 + threadIdx.x;
    int b = bn >> 16, n = bn & 0xFFFF;
    float4* po = reinterpret_cast<float4*>(out + (size_t)bn * C);
    if (n < nv[b]) {
        const float4* r = reinterpret_cast<const float4*>(t + (size_t)bn * C);
        #pragma unroll
        for (int k = 0; k < 4; ++k) {
            float4 v = r[k];
            float4 y;
            y.x = fmaxf(0.0f, v.x * sA[4*k+0] + sA[16+4*k+0]);
            y.y = fmaxf(0.0f, v.y * sA[4*k+1] + sA[16+4*k+1]);
            y.z = fmaxf(0.0f, v.z * sA[4*k+2] + sA[16+4*k+2]);
            y.w = fmaxf(0.0f, v.w * sA[4*k+3] + sA[16+4*k+3]);
            po[k] = y;
        }
    } else {
        float4 z = make_float4(0.f, 0.f, 0.f, 0.f);
        #pragma unroll
        for (int k = 0; k < 4; ++k) po[k] = z;
    }
}

// ---------------- launch ----------------
extern "C" void kernel_launch(void* const* d_in, const int* in_sizes, int n_in,
                              void* d_out, int out_size) {
    const float* feats = (const float*)d_in[0];
    const int*   xyz   = (const int*)  d_in[1];
    const int*   nv    = (const int*)  d_in[2];
    const float* w0    = (const float*)d_in[3];
    const float* w1    = (const float*)d_in[4];
    const float* nw0   = (const float*)d_in[5];
    const float* nw1   = (const float*)d_in[6];
    const float* ga0   = (const float*)d_in[7];
    const float* be0   = (const float*)d_in[8];
    const float* ga1   = (const float*)d_in[9];
    const float* be1   = (const float*)d_in[10];
    float* out = (float*)d_out;

    float *t0, *t1, *aff;
    cudaGetSymbolAddress((void**)&t0,  g_t0);
    cudaGetSymbolAddress((void**)&t1,  g_t1);
    cudaGetSymbolAddress((void**)&aff, g_affine);

    cudaFuncSetAttribute(k_conv<false>, cudaFuncAttributeMaxDynamicSharedMemorySize, SM_BYTES);
    cudaFuncSetAttribute(k_conv<true>,  cudaFuncAttributeMaxDynamicSharedMemorySize, SM_BYTES);

    // launch index:                                    (ncu -s 5 -c 1 -> #5 = conv<true>)
    k_init_map<<<(NB*G3/4)/256, 256>>>();             // 0
    k_scatter <<<BNTOT/256, 256>>>(xyz, nv);          // 1
    k_build   <<<NTILES, 1024>>>(xyz, nv);            // 2

    // g_stats starts zeroed (BSS on first call, k_finalize re-zeroes thereafter)
    k_conv<false><<<NTILES*2, 256, SM_BYTES>>>(feats, w0, nw0, nullptr, t0); // 3
    k_finalize<<<1, 32>>>(ga0, be0, nv);                                     // 4
    k_conv<true> <<<NTILES*2, 256, SM_BYTES>>>(t0, w1, nw1, aff, t1);        // 5
    k_finalize<<<1, 32>>>(ga1, be1, nv);                                     // 6
    k_apply<<<BNTOT/256, 256>>>(t1, nv, out);                                // 7
}

// round 14
// speedup vs baseline: 1.0777x; 1.0777x over previous
#include <cuda_runtime.h>
#include <cstdint>

#define NB     8
#define NVOX   65536
#define GRIDSZ 64
#define G3     (GRIDSZ*GRIDSZ*GRIDSZ)
#define BNTOT  (NB*NVOX)
#define C      16
#define EPSF   1e-3f
#define TILE   1024
#define NTILES (BNTOT/TILE)          // 512
#define NBKT   (NTILES*27)           // 13824

// ---------------- static scratch (no allocation) ----------------
__device__ int   g_idx_map[NB*G3];                 // 8.4 MB
__device__ int   g_pairs[(size_t)NBKT*TILE];       // 56.6 MB: (local<<16)|in_row per (tile,o)
__device__ int   g_cnt[NBKT];
__device__ int   g_nbmask[BNTOT];                  // 2 MB: 27-bit active-neighbor mask
__device__ float g_t0[(size_t)BNTOT*C];            // 33.5 MB pre-BN layer-0
__device__ float g_t1[(size_t)BNTOT*C];            // 33.5 MB pre-BN layer-1
__device__ float g_stats[2*C];                     // [sum16, sumsq16] (zeroed by finalize)
__device__ float g_affine[2*C];                    // [A16, B16]

// ---------------- f32x2 helpers ----------------
__device__ __forceinline__ unsigned long long fma2(unsigned long long a,
                                                   unsigned long long b,
                                                   unsigned long long c) {
    unsigned long long d;
    asm("fma.rn.f32x2 %0, %1, %2, %3;" : "=l"(d) : "l"(a), "l"(b), "l"(c));
    return d;
}
__device__ __forceinline__ unsigned long long bcast2(float x) {
    unsigned long long d; unsigned r = __float_as_uint(x);
    asm("mov.b64 %0, {%1, %2};" : "=l"(d) : "r"(r), "r"(r));
    return d;
}

// ---------------- phase 0: hash map ----------------
__global__ void k_init_map() {
    int i = blockIdx.x * blockDim.x + threadIdx.x;
    reinterpret_cast<int4*>(g_idx_map)[i] = make_int4(-1, -1, -1, -1);
}

__global__ void k_scatter(const int* __restrict__ xyz, const int* __restrict__ nv) {
    int bn = blockIdx.x * blockDim.x + threadIdx.x;
    int b = bn >> 16, n = bn & 0xFFFF;
    if (n < nv[b]) {
        const int* c = xyz + (size_t)bn * 3;
        g_idx_map[b * G3 + c[0] * (GRIDSZ*GRIDSZ) + c[1] * GRIDSZ + c[2]] = n;
    }
}

// ---------------- phase 1: per-(tile,o) rulebook + neighbor mask ----------------
__global__ __launch_bounds__(1024)
void k_build(const int* __restrict__ xyz, const int* __restrict__ nv) {
    __shared__ int s_cnt[27];
    int tid = threadIdx.x;
    if (tid < 27) s_cnt[tid] = 0;
    __syncthreads();

    int bn = blockIdx.x * TILE + tid;
    int b  = bn >> 16, n = bn & 0xFFFF;
    bool valid = n < nv[b];
    int x = 0, y = 0, z = 0, base = b * G3;
    if (valid) {
        const int* c = xyz + (size_t)bn * 3;
        x = c[0]; y = c[1]; z = c[2];
    }
    int tilebase = blockIdx.x * 27;
    int lane = tid & 31;
    int mask = 0;

    #pragma unroll
    for (int o = 0; o < 27; ++o) {
        int dx = o / 9 - 1, dy = (o / 3) % 3 - 1, dz = o % 3 - 1;
        int idx = -1;
        if (valid) {
            int nx = x + dx, ny = y + dy, nz = z + dz;
            if (((unsigned)nx < GRIDSZ) & ((unsigned)ny < GRIDSZ) & ((unsigned)nz < GRIDSZ))
                idx = g_idx_map[base + nx * (GRIDSZ*GRIDSZ) + ny * GRIDSZ + nz];
        }
        unsigned m = __ballot_sync(0xFFFFFFFFu, idx >= 0);
        if (m) {
            int leader = __ffs(m) - 1;
            int basepos = 0;
            if (lane == leader) basepos = atomicAdd(&s_cnt[o], __popc(m));
            basepos = __shfl_sync(0xFFFFFFFFu, basepos, leader);
            if (idx >= 0) {
                int nbefore = __popc(m & ((1u << lane) - 1u));
                g_pairs[((size_t)(tilebase + o) << 10) + basepos + nbefore] = (tid << 16) | idx;
                mask |= 1 << o;
            }
        }
    }
    g_nbmask[bn] = mask;
    __syncthreads();
    if (tid < 27) g_cnt[tilebase + tid] = s_cnt[tid];
}

// ---------------- conv: register-tiled warp GEMM over rulebook ----------------
// lane = (cg = lane>>3, mg = lane&7); lane computes pairs {mg+8p} x channels [cg*4, cg*4+4)
// smem floats: acc TILE*16 (xor quarter swizzle) | w 27*256 | stage 8*32*16 (xor) | nw 32 | aff 32
#define SM_FLOATS (TILE*16 + 27*256 + 8*32*16 + 32 + 32)
#define SM_BYTES  (SM_FLOATS * 4)

template<bool AFF>
__global__ __launch_bounds__(256, 2)
void k_conv(const float* __restrict__ feats, const float* __restrict__ w,
            const float* __restrict__ nw, const float* __restrict__ affine,
            float* __restrict__ tout) {
    extern __shared__ float sm[];
    float* s_acc   = sm;                      // row r: logical quarter q at r*16+((q^(r&3))<<2)
    float* s_w     = sm + TILE*16;
    float* s_stage = s_w + 27*256;            // 8 warps x 32 rows x 16 (xor quarter swizzle)
    float* s_nw    = s_stage + 8*32*16;
    float* s_aff   = s_nw + 32;

    int tid = threadIdx.x;
    for (int i = tid; i < 27*256; i += 256) s_w[i] = w[i];
    if (tid < 27) s_nw[tid] = nw[tid];
    if (AFF && tid < 32) s_aff[tid] = affine[tid];
    for (int i = tid; i < TILE*16; i += 256) s_acc[i] = 0.0f;
    __syncthreads();

    int tile = blockIdx.x;
    int b    = tile >> 6;                     // 64 tiles per batch
    const float* fb = feats + (size_t)b * NVOX * C;

    int wi = tid >> 5, lane = tid & 31;
    float* stW = s_stage + wi * (32 * 16);
    int qsub = lane & 3;                      // gather: quarter this lane loads
    int rsub = lane >> 2;                     // gather: row group
    int cg   = lane >> 3;                     // compute: channel group (4 co)
    int mg   = lane & 7;                      // compute: pair group (pairs mg+8p)

    float4 affA, affB;
    if (AFF) {
        affA = *reinterpret_cast<const float4*>(s_aff + qsub * 4);
        affB = *reinterpret_cast<const float4*>(s_aff + 16 + qsub * 4);
    }

    for (int o = 0; o < 27; ++o) {
        int bkt = tile * 27 + o;
        int cnt = g_cnt[bkt];
        const int* pl = g_pairs + ((size_t)bkt << 10);

        int base = wi * 32;
        if (base < cnt) {
            // hoist this o's weights for lane's 4 channels: W[ci][cg*4..+3], once per o
            ulonglong2 wr[16];
            #pragma unroll
            for (int ci = 0; ci < 16; ++ci)
                wr[ci] = *reinterpret_cast<const ulonglong2*>(s_w + o * 256 + ci * 16 + cg * 4);

            int pc = (base + lane < cnt) ? pl[base + lane] : 0;
            float4 V[4];
            #pragma unroll
            for (int k = 0; k < 4; ++k) {
                int rk = __shfl_sync(0xFFFFFFFFu, pc, rsub + 8*k) & 0xFFFF;
                V[k] = __ldg(reinterpret_cast<const float4*>(fb + (size_t)rk * C) + qsub);
            }
            while (base < cnt) {
                __syncwarp();                 // WAR on stage
                #pragma unroll
                for (int k = 0; k < 4; ++k) {
                    int r = rsub + 8*k;
                    float4 sv = V[k];
                    if (AFF) {
                        sv.x = fmaxf(0.f, sv.x * affA.x + affB.x);
                        sv.y = fmaxf(0.f, sv.y * affA.y + affB.y);
                        sv.z = fmaxf(0.f, sv.z * affA.z + affB.z);
                        sv.w = fmaxf(0.f, sv.w * affA.w + affB.w);
                    }
                    *reinterpret_cast<float4*>(stW + r * 16 + ((qsub ^ (r & 3)) << 2)) = sv;
                }
                __syncwarp();                 // stage visible

                // prefetch next chunk under compute
                int nbase = base + 256;
                int pn = (nbase + lane < cnt) ? pl[nbase + lane] : 0;
                #pragma unroll
                for (int k = 0; k < 4; ++k) {
                    int rk = __shfl_sync(0xFFFFFFFFu, pn, rsub + 8*k) & 0xFFFF;
                    V[k] = __ldg(reinterpret_cast<const float4*>(fb + (size_t)rk * C) + qsub);
                }

                // compute: 4 pairs x 4 channels per lane
                #pragma unroll
                for (int p = 0; p < 4; ++p) {
                    int pi = mg + 8*p;
                    int pcp = __shfl_sync(0xFFFFFFFFu, pc, pi);   // uniform exec
                    if (base + pi < cnt) {
                        float fv[16];
                        #pragma unroll
                        for (int q = 0; q < 4; ++q)
                            *reinterpret_cast<float4*>(fv + 4*q) =
                                *reinterpret_cast<const float4*>(stW + pi * 16 + ((q ^ (pi & 3)) << 2));
                        int local = pcp >> 16;
                        float* arow = s_acc + local * 16 + ((cg ^ (local & 3)) << 2);
                        ulonglong2 a = *reinterpret_cast<ulonglong2*>(arow);
                        unsigned long long ax = a.x, ay = a.y;
                        #pragma unroll
                        for (int ci = 0; ci < 16; ++ci) {
                            unsigned long long am = bcast2(fv[ci]);
                            ax = fma2(am, wr[ci].x, ax);
                            ay = fma2(am, wr[ci].y, ay);
                        }
                        *reinterpret_cast<ulonglong2*>(arow) = make_ulonglong2(ax, ay);
                    }
                }
                base = nbase; pc = pn;
            }
        }
        __syncthreads();   // o -> o+1 ordering (same out row across o's)
    }

    // epilogue: norm-div (from neighbor mask), write t, BN partials
    float ps[16], pq[16];
    #pragma unroll
    for (int c2 = 0; c2 < 16; ++c2) { ps[c2] = 0.0f; pq[c2] = 0.0f; }

    #pragma unroll
    for (int k = 0; k < 4; ++k) {
        int i = tid + k * 256;
        int m = g_nbmask[tile * TILE + i];
        float nsum = 0.0f;
        #pragma unroll
        for (int o = 0; o < 27; ++o)
            nsum += ((m >> o) & 1) ? s_nw[o] : 0.0f;
        float inv = 1.0f / (1.0f + fabsf(nsum));
        int s = i & 3;
        const float* ar = s_acc + i * 16;
        float4* to = reinterpret_cast<float4*>(tout + (size_t)(tile * TILE + i) * C);
        #pragma unroll
        for (int q = 0; q < 4; ++q) {
            float4 v = *reinterpret_cast<const float4*>(ar + ((q ^ s) << 2));
            float x0 = v.x*inv, x1 = v.y*inv, x2 = v.z*inv, x3 = v.w*inv;
            to[q] = make_float4(x0, x1, x2, x3);
            ps[4*q+0] += x0; pq[4*q+0] += x0*x0;
            ps[4*q+1] += x1; pq[4*q+1] += x1*x1;
            ps[4*q+2] += x2; pq[4*q+2] += x2*x2;
            ps[4*q+3] += x3; pq[4*q+3] += x3*x3;
        }
    }
    #pragma unroll
    for (int off = 16; off; off >>= 1) {
        #pragma unroll
        for (int c2 = 0; c2 < 16; ++c2) {
            ps[c2] += __shfl_xor_sync(0xFFFFFFFFu, ps[c2], off);
            pq[c2] += __shfl_xor_sync(0xFFFFFFFFu, pq[c2], off);
        }
    }
    __syncthreads();
    float* s_red = s_stage;            // reuse stage: 8 warps x 32 floats
    if ((tid & 31) == 0) {
        #pragma unroll
        for (int c2 = 0; c2 < 16; ++c2) {
            s_red[wi*32 + c2]      = ps[c2];
            s_red[wi*32 + 16 + c2] = pq[c2];
        }
    }
    __syncthreads();
    if (tid < 32) {
        float a = 0.0f;
        #pragma unroll
        for (int w8 = 0; w8 < 8; ++w8) a += s_red[w8*32 + tid];
        atomicAdd(&g_stats[tid], a);
    }
}

// ---------------- BN finalize (reads stats, writes affine, re-zeroes stats) ----------------
__global__ void k_finalize(const float* __restrict__ gamma,
                           const float* __restrict__ beta,
                           const int* __restrict__ nv) {
    int i = threadIdx.x;   // 32 threads
    float A = 0.0f, Bv = 0.0f;
    if (i < C) {
        float cnt = 0.0f;
        #pragma unroll
        for (int b = 0; b < NB; ++b) cnt += (float)nv[b];
        float mean = g_stats[i] / cnt;
        float var  = g_stats[C + i] / cnt - mean * mean;
        A  = rsqrtf(var + EPSF) * gamma[i];
        Bv = beta[i] - mean * A;
    }
    __syncwarp();
    if (i < C) { g_affine[i] = A; g_affine[C + i] = Bv; }
    g_stats[i] = 0.0f;     // replay-safe
}

// ---------------- final affine+relu+mask ----------------
__global__ __launch_bounds__(256)
void k_apply(const float* __restrict__ t, const int* __restrict__ nv,
             float* __restrict__ out) {
    __shared__ float sA[32];
    if (threadIdx.x < 32) sA[threadIdx.x] = g_affine[threadIdx.x];
    __syncthreads();
    int bn = blockIdx.x * 256 + threadIdx.x;
    int b = bn >> 16, n = bn & 0xFFFF;
    float4* po = reinterpret_cast<float4*>(out + (size_t)bn * C);
    if (n < nv[b]) {
        const float4* r = reinterpret_cast<const float4*>(t + (size_t)bn * C);
        #pragma unroll
        for (int k = 0; k < 4; ++k) {
            float4 v = r[k];
            float4 y;
            y.x = fmaxf(0.0f, v.x * sA[4*k+0] + sA[16+4*k+0]);
            y.y = fmaxf(0.0f, v.y * sA[4*k+1] + sA[16+4*k+1]);
            y.z = fmaxf(0.0f, v.z * sA[4*k+2] + sA[16+4*k+2]);
            y.w = fmaxf(0.0f, v.w * sA[4*k+3] + sA[16+4*k+3]);
            po[k] = y;
        }
    } else {
        float4 z = make_float4(0.f, 0.f, 0.f, 0.f);
        #pragma unroll
        for (int k = 0; k < 4; ++k) po[k] = z;
    }
}

// ---------------- launch ----------------
extern "C" void kernel_launch(void* const* d_in, const int* in_sizes, int n_in,
                              void* d_out, int out_size) {
    const float* feats = (const float*)d_in[0];
    const int*   xyz   = (const int*)  d_in[1];
    const int*   nv    = (const int*)  d_in[2];
    const float* w0    = (const float*)d_in[3];
    const float* w1    = (const float*)d_in[4];
    const float* nw0   = (const float*)d_in[5];
    const float* nw1   = (const float*)d_in[6];
    const float* ga0   = (const float*)d_in[7];
    const float* be0   = (const float*)d_in[8];
    const float* ga1   = (const float*)d_in[9];
    const float* be1   = (const float*)d_in[10];
    float* out = (float*)d_out;

    float *t0, *t1, *aff;
    cudaGetSymbolAddress((void**)&t0,  g_t0);
    cudaGetSymbolAddress((void**)&t1,  g_t1);
    cudaGetSymbolAddress((void**)&aff, g_affine);

    cudaFuncSetAttribute(k_conv<false>, cudaFuncAttributeMaxDynamicSharedMemorySize, SM_BYTES);
    cudaFuncSetAttribute(k_conv<true>,  cudaFuncAttributeMaxDynamicSharedMemorySize, SM_BYTES);

    // launch index:                                    (ncu -s 5 -c 1 -> #5 = conv<true>)
    k_init_map<<<(NB*G3/4)/256, 256>>>();             // 0
    k_scatter <<<BNTOT/256, 256>>>(xyz, nv);          // 1
    k_build   <<<NTILES, 1024>>>(xyz, nv);            // 2

    // g_stats starts zeroed (BSS on first call, k_finalize re-zeroes thereafter)
    k_conv<false><<<NTILES, 256, SM_BYTES>>>(feats, w0, nw0, nullptr, t0);  // 3
    k_finalize<<<1, 32>>>(ga0, be0, nv);                                    // 4
    k_conv<true> <<<NTILES, 256, SM_BYTES>>>(t0, w1, nw1, aff, t1);         // 5
    k_finalize<<<1, 32>>>(ga1, be1, nv);                                    // 6
    k_apply<<<BNTOT/256, 256>>>(t1, nv, out);                               // 7
}

// round 15
// speedup vs baseline: 1.3473x; 1.2501x over previous
#include <cuda_runtime.h>
#include <cstdint>

#define NB     8
#define NVOX   65536
#define GRIDSZ 64
#define G3     (GRIDSZ*GRIDSZ*GRIDSZ)
#define BNTOT  (NB*NVOX)
#define C      16
#define EPSF   1e-3f
#define TILE   1024
#define NTILES (BNTOT/TILE)          // 512
#define NBKT2  (NTILES*8*27)         // 110592 buckets (tile, warp, o), slab 128

// ---------------- static scratch (no allocation) ----------------
__device__ int   g_idx_map[NB*G3];                 // 8.4 MB
__device__ int   g_pairs[(size_t)NBKT2*128];       // 56.6 MB: (local<<16)|in_row
__device__ int   g_cnt[NBKT2];
__device__ int   g_nbmask[BNTOT];                  // 2 MB: 27-bit active-neighbor mask
__device__ float g_t0[(size_t)BNTOT*C];            // 33.5 MB pre-BN layer-0
__device__ float g_t1[(size_t)BNTOT*C];            // 33.5 MB pre-BN layer-1
__device__ float g_stats[2*C];                     // [sum16, sumsq16] (zeroed by finalize)
__device__ float g_affine[2*C];                    // [A16, B16]

// ---------------- f32x2 helpers ----------------
__device__ __forceinline__ unsigned long long fma2(unsigned long long a,
                                                   unsigned long long b,
                                                   unsigned long long c) {
    unsigned long long d;
    asm("fma.rn.f32x2 %0, %1, %2, %3;" : "=l"(d) : "l"(a), "l"(b), "l"(c));
    return d;
}
__device__ __forceinline__ unsigned long long bcast2(float x) {
    unsigned long long d; unsigned r = __float_as_uint(x);
    asm("mov.b64 %0, {%1, %2};" : "=l"(d) : "r"(r), "r"(r));
    return d;
}

// ---------------- phase 0: hash map ----------------
__global__ void k_init_map() {
    int i = blockIdx.x * blockDim.x + threadIdx.x;
    reinterpret_cast<int4*>(g_idx_map)[i] = make_int4(-1, -1, -1, -1);
}

__global__ void k_scatter(const int* __restrict__ xyz, const int* __restrict__ nv) {
    int bn = blockIdx.x * blockDim.x + threadIdx.x;
    int b = bn >> 16, n = bn & 0xFFFF;
    if (n < nv[b]) {
        const int* c = xyz + (size_t)bn * 3;
        g_idx_map[b * G3 + c[0] * (GRIDSZ*GRIDSZ) + c[1] * GRIDSZ + c[2]] = n;
    }
}

// ---------------- phase 1: rulebook bucketed by (tile, warp, o) ----------------
__global__ __launch_bounds__(1024)
void k_build(const int* __restrict__ xyz, const int* __restrict__ nv) {
    __shared__ int s_cnt[8*27];
    int tid = threadIdx.x;
    for (int i = tid; i < 8*27; i += 1024) s_cnt[i] = 0;
    __syncthreads();

    int bn = blockIdx.x * TILE + tid;
    int b  = bn >> 16, n = bn & 0xFFFF;
    bool valid = n < nv[b];
    int x = 0, y = 0, z = 0, base = b * G3;
    if (valid) {
        const int* c = xyz + (size_t)bn * 3;
        x = c[0]; y = c[1]; z = c[2];
    }
    int wi   = tid >> 7;                    // warp-owner of this output row (warp-uniform)
    int lane = tid & 31;
    int mask = 0;

    #pragma unroll
    for (int o = 0; o < 27; ++o) {
        int dx = o / 9 - 1, dy = (o / 3) % 3 - 1, dz = o % 3 - 1;
        int idx = -1;
        if (valid) {
            int nx = x + dx, ny = y + dy, nz = z + dz;
            if (((unsigned)nx < GRIDSZ) & ((unsigned)ny < GRIDSZ) & ((unsigned)nz < GRIDSZ))
                idx = g_idx_map[base + nx * (GRIDSZ*GRIDSZ) + ny * GRIDSZ + nz];
        }
        unsigned m = __ballot_sync(0xFFFFFFFFu, idx >= 0);
        if (m) {
            int leader = __ffs(m) - 1;
            int basepos = 0;
            if (lane == leader) basepos = atomicAdd(&s_cnt[wi*27 + o], __popc(m));
            basepos = __shfl_sync(0xFFFFFFFFu, basepos, leader);
            if (idx >= 0) {
                int nbefore = __popc(m & ((1u << lane) - 1u));
                size_t bkt = (size_t)(blockIdx.x*8 + wi)*27 + o;
                g_pairs[(bkt << 7) + basepos + nbefore] = (tid << 16) | idx;
                mask |= 1 << o;
            }
        }
    }
    g_nbmask[bn] = mask;
    __syncthreads();
    if (tid < 8*27) g_cnt[blockIdx.x * (8*27) + tid] = s_cnt[tid];
}

// ---------------- conv: barrier-free warp GEMM, cross-o pipelined, shfl fv ----------------
// smem floats: acc 1024*20 | w 27*256 | nw 32 | aff 32
#define SM_FLOATS (TILE*20 + 27*256 + 32 + 32)
#define SM_BYTES  (SM_FLOATS * 4)

template<bool AFF>
__global__ __launch_bounds__(256, 2)
void k_conv(const float* __restrict__ feats, const float* __restrict__ w,
            const float* __restrict__ nw, const float* __restrict__ affine,
            float* __restrict__ tout) {
    extern __shared__ float sm[];
    float* s_acc = sm;                     // row r: 16 ch at r*20 .. r*20+16
    float* s_w   = sm + TILE*20;
    float* s_nw  = s_w + 27*256;
    float* s_aff = s_nw + 32;

    int tid = threadIdx.x;
    for (int i = tid; i < 27*256; i += 256) s_w[i] = w[i];
    if (tid < 27) s_nw[tid] = nw[tid];
    if (AFF && tid < 32) s_aff[tid] = affine[tid];
    for (int i = tid; i < TILE*20; i += 256) s_acc[i] = 0.0f;
    __syncthreads();

    int tile = blockIdx.x;
    int b    = tile >> 6;                  // 64 tiles per batch
    const float* fb = feats + (size_t)b * NVOX * C;

    int wi = tid >> 5, lane = tid & 31;
    int qsub = lane & 3;                   // gather: quarter this lane loads
    int rsub = lane >> 2;                  // gather: pair-slot group
    int cg   = lane >> 3;                  // compute: channel group (4 co)
    int mg   = lane & 7;                   // compute: pair group (pairs mg+8p)
    int tw   = (tile << 3) | wi;

    float4 affA = make_float4(0,0,0,0), affB = make_float4(0,0,0,0);
    if (AFF) {
        affA = *reinterpret_cast<const float4*>(s_aff + qsub * 4);
        affB = *reinterpret_cast<const float4*>(s_aff + 16 + qsub * 4);
    }

    int mycnt = (lane < 27) ? g_cnt[tw*27 + lane] : 0;

    // fetch one 32-pair chunk of bucket (tw, o) at offset bb
    auto fetch = [&](int o, int bb, int cnto, int& pcN, float4* VN) {
        const int* pl = g_pairs + ((size_t)(tw*27 + o) << 7);
        pcN = (bb + lane < cnto) ? pl[bb + lane] : 0;
        #pragma unroll
        for (int k = 0; k < 4; ++k) {
            int rk = __shfl_sync(0xFFFFFFFFu, pcN, rsub + 8*k) & 0xFFFF;
            float4 v = __ldg(reinterpret_cast<const float4*>(fb + (size_t)rk * C) + qsub);
            if (AFF) {
                v.x = fmaxf(0.f, v.x * affA.x + affB.x);
                v.y = fmaxf(0.f, v.y * affA.y + affB.y);
                v.z = fmaxf(0.f, v.z * affA.z + affB.z);
                v.w = fmaxf(0.f, v.w * affA.w + affB.w);
            }
            VN[k] = v;
        }
    };

    // software pipeline across chunks AND o's (no barriers in this loop)
    int o_f = 0, b_f = 0;
    int pc = 0; float4 V[4];
    fetch(0, 0, __shfl_sync(0xFFFFFFFFu, mycnt, 0), pc, V);

    ulonglong2 wr[16];
    while (o_f < 27) {
        int o_c = o_f, b_c = b_f;
        int cnt_c = __shfl_sync(0xFFFFFFFFu, mycnt, o_c);
        if (b_c + 32 < cnt_c) { b_f = b_c + 32; }
        else                  { o_f = o_c + 1; b_f = 0; }

        int pcN = 0; float4 VN[4];
        if (o_f < 27)
            fetch(o_f, b_f, __shfl_sync(0xFFFFFFFFu, mycnt, o_f), pcN, VN);

        if (b_c == 0 && cnt_c > 0) {
            #pragma unroll
            for (int ci = 0; ci < 16; ++ci)
                wr[ci] = *reinterpret_cast<const ulonglong2*>(s_w + o_c*256 + ci*16 + cg*4);
        }

        #pragma unroll
        for (int p = 0; p < 4; ++p) {
            if (b_c + 8*p < cnt_c) {                       // uniform
                int pi  = mg + 8*p;
                int pcp = __shfl_sync(0xFFFFFFFFu, pc, pi);
                float fv[16];
                #pragma unroll
                for (int qq = 0; qq < 4; ++qq) {
                    int src = (mg << 2) | qq;
                    fv[qq*4+0] = __shfl_sync(0xFFFFFFFFu, V[p].x, src);
                    fv[qq*4+1] = __shfl_sync(0xFFFFFFFFu, V[p].y, src);
                    fv[qq*4+2] = __shfl_sync(0xFFFFFFFFu, V[p].z, src);
                    fv[qq*4+3] = __shfl_sync(0xFFFFFFFFu, V[p].w, src);
                }
                if (b_c + pi < cnt_c) {                    // per-lane
                    int local = pcp >> 16;
                    float* arow = s_acc + local * 20 + cg * 4;
                    ulonglong2 a = *reinterpret_cast<ulonglong2*>(arow);
                    unsigned long long ax = a.x, ay = a.y;
                    #pragma unroll
                    for (int ci = 0; ci < 16; ++ci) {
                        unsigned long long am = bcast2(fv[ci]);
                        ax = fma2(am, wr[ci].x, ax);
                        ay = fma2(am, wr[ci].y, ay);
                    }
                    *reinterpret_cast<ulonglong2*>(arow) = make_ulonglong2(ax, ay);
                }
            }
        }
        pc = pcN;
        V[0] = VN[0]; V[1] = VN[1]; V[2] = VN[2]; V[3] = VN[3];
    }
    __syncthreads();   // all warps done accumulating

    // epilogue: norm-div (from neighbor mask), write t, BN partials
    float ps[16], pq[16];
    #pragma unroll
    for (int c2 = 0; c2 < 16; ++c2) { ps[c2] = 0.0f; pq[c2] = 0.0f; }

    #pragma unroll
    for (int k = 0; k < 4; ++k) {
        int i = tid + k * 256;
        int m = g_nbmask[tile * TILE + i];
        float nsum = 0.0f;
        #pragma unroll
        for (int o = 0; o < 27; ++o)
            nsum += ((m >> o) & 1) ? s_nw[o] : 0.0f;
        float inv = 1.0f / (1.0f + fabsf(nsum));
        const float* ar = s_acc + i * 20;
        float4* to = reinterpret_cast<float4*>(tout + (size_t)(tile * TILE + i) * C);
        #pragma unroll
        for (int q = 0; q < 4; ++q) {
            float4 v = *reinterpret_cast<const float4*>(ar + q * 4);
            float x0 = v.x*inv, x1 = v.y*inv, x2 = v.z*inv, x3 = v.w*inv;
            to[q] = make_float4(x0, x1, x2, x3);
            ps[4*q+0] += x0; pq[4*q+0] += x0*x0;
            ps[4*q+1] += x1; pq[4*q+1] += x1*x1;
            ps[4*q+2] += x2; pq[4*q+2] += x2*x2;
            ps[4*q+3] += x3; pq[4*q+3] += x3*x3;
        }
    }
    #pragma unroll
    for (int off = 16; off; off >>= 1) {
        #pragma unroll
        for (int c2 = 0; c2 < 16; ++c2) {
            ps[c2] += __shfl_xor_sync(0xFFFFFFFFu, ps[c2], off);
            pq[c2] += __shfl_xor_sync(0xFFFFFFFFu, pq[c2], off);
        }
    }
    float* s_red = s_w;                // weights no longer needed
    if ((tid & 31) == 0) {
        #pragma unroll
        for (int c2 = 0; c2 < 16; ++c2) {
            s_red[wi*32 + c2]      = ps[c2];
            s_red[wi*32 + 16 + c2] = pq[c2];
        }
    }
    __syncthreads();
    if (tid < 32) {
        float a = 0.0f;
        #pragma unroll
        for (int w8 = 0; w8 < 8; ++w8) a += s_red[w8*32 + tid];
        atomicAdd(&g_stats[tid], a);
    }
}

// ---------------- BN finalize (reads stats, writes affine, re-zeroes stats) ----------------
__global__ void k_finalize(const float* __restrict__ gamma,
                           const float* __restrict__ beta,
                           const int* __restrict__ nv) {
    int i = threadIdx.x;   // 32 threads
    float A = 0.0f, Bv = 0.0f;
    if (i < C) {
        float cnt = 0.0f;
        #pragma unroll
        for (int b = 0; b < NB; ++b) cnt += (float)nv[b];
        float mean = g_stats[i] / cnt;
        float var  = g_stats[C + i] / cnt - mean * mean;
        A  = rsqrtf(var + EPSF) * gamma[i];
        Bv = beta[i] - mean * A;
    }
    __syncwarp();
    if (i < C) { g_affine[i] = A; g_affine[C + i] = Bv; }
    g_stats[i] = 0.0f;     // replay-safe
}

// ---------------- final affine+relu+mask ----------------
__global__ __launch_bounds__(256)
void k_apply(const float* __restrict__ t, const int* __restrict__ nv,
             float* __restrict__ out) {
    __shared__ float sA[32];
    if (threadIdx.x < 32) sA[threadIdx.x] = g_affine[threadIdx.x];
    __syncthreads();
    int bn = blockIdx.x * 256 + threadIdx.x;
    int b = bn >> 16, n = bn & 0xFFFF;
    float4* po = reinterpret_cast<float4*>(out + (size_t)bn * C);
    if (n < nv[b]) {
        const float4* r = reinterpret_cast<const float4*>(t + (size_t)bn * C);
        #pragma unroll
        for (int k = 0; k < 4; ++k) {
            float4 v = r[k];
            float4 y;
            y.x = fmaxf(0.0f, v.x * sA[4*k+0] + sA[16+4*k+0]);
            y.y = fmaxf(0.0f, v.y * sA[4*k+1] + sA[16+4*k+1]);
            y.z = fmaxf(0.0f, v.z * sA[4*k+2] + sA[16+4*k+2]);
            y.w = fmaxf(0.0f, v.w * sA[4*k+3] + sA[16+4*k+3]);
            po[k] = y;
        }
    } else {
        float4 z = make_float4(0.f, 0.f, 0.f, 0.f);
        #pragma unroll
        for (int k = 0; k < 4; ++k) po[k] = z;
    }
}

// ---------------- launch ----------------
extern "C" void kernel_launch(void* const* d_in, const int* in_sizes, int n_in,
                              void* d_out, int out_size) {
    const float* feats = (const float*)d_in[0];
    const int*   xyz   = (const int*)  d_in[1];
    const int*   nv    = (const int*)  d_in[2];
    const float* w0    = (const float*)d_in[3];
    const float* w1    = (const float*)d_in[4];
    const float* nw0   = (const float*)d_in[5];
    const float* nw1   = (const float*)d_in[6];
    const float* ga0   = (const float*)d_in[7];
    const float* be0   = (const float*)d_in[8];
    const float* ga1   = (const float*)d_in[9];
    const float* be1   = (const float*)d_in[10];
    float* out = (float*)d_out;

    float *t0, *t1, *aff;
    cudaGetSymbolAddress((void**)&t0,  g_t0);
    cudaGetSymbolAddress((void**)&t1,  g_t1);
    cudaGetSymbolAddress((void**)&aff, g_affine);

    cudaFuncSetAttribute(k_conv<false>, cudaFuncAttributeMaxDynamicSharedMemorySize, SM_BYTES);
    cudaFuncSetAttribute(k_conv<true>,  cudaFuncAttributeMaxDynamicSharedMemorySize, SM_BYTES);

    // launch index:                                    (ncu -s 5 -c 1 -> #5 = conv<true>)
    k_init_map<<<(NB*G3/4)/256, 256>>>();             // 0
    k_scatter <<<BNTOT/256, 256>>>(xyz, nv);          // 1
    k_build   <<<NTILES, 1024>>>(xyz, nv);            // 2

    // g_stats starts zeroed (BSS on first call, k_finalize re-zeroes thereafter)
    k_conv<false><<<NTILES, 256, SM_BYTES>>>(feats, w0, nw0, nullptr, t0);  // 3
    k_finalize<<<1, 32>>>(ga0, be0, nv);                                    // 4
    k_conv<true> <<<NTILES, 256, SM_BYTES>>>(t0, w1, nw1, aff, t1);         // 5
    k_finalize<<<1, 32>>>(ga1, be1, nv);                                    // 6
    k_apply<<<BNTOT/256, 256>>>(t1, nv, out);                               // 7
}